// round 1
// baseline (speedup 1.0000x reference)
#include <cuda_runtime.h>
#include <cstddef>

// Problem constants
#define BATCH 8
#define SEQ   4096
#define DIN   512
#define HID   512
#define MROWS (BATCH*SEQ)      // 32768
#define NCOLS (2*HID)          // 1024

// Scratch (device globals -- allocation-free per harness rules)
__device__ float g_gh[(size_t)MROWS * NCOLS];  // 128 MB: pre-activation gate/hidden
__device__ float g_h1[(size_t)MROWS * HID];    //  64 MB: layer-0 output / layer-1 input

// ---------------------------------------------------------------------------
// SGEMM: C(M x N) = A(M x K) @ W(N x K)^T + bias,  fp32
// Classic 128x128x8 tile, 256 threads, 8x8 per thread.
// Ain == nullptr  ->  read A from g_h1 (layer 1). C is always g_gh.
// ---------------------------------------------------------------------------
#define BM 128
#define BN 128
#define BK 8
#define TM 8
#define TN 8

__global__ __launch_bounds__(256) void sgemm_bias_kernel(
    const float* __restrict__ Ain,
    const float* __restrict__ W,
    const float* __restrict__ bias,
    int M, int N, int K)
{
    const float* A = Ain ? Ain : g_h1;
    float* C = g_gh;

    __shared__ float As[BK][BM];
    __shared__ float Bs[BK][BN];

    const int tid = threadIdx.x;
    const int tx = tid & 15;        // 0..15  -> N direction
    const int ty = tid >> 4;        // 0..15  -> M direction
    const int rowBase = blockIdx.y * BM;
    const int colBase = blockIdx.x * BN;

    // Cooperative loads: 256 threads, one float4 each per tile
    const int ldRow = tid >> 1;           // 0..127
    const int ldCol = (tid & 1) * 4;      // 0 or 4

    const float* Aptr = A + (size_t)(rowBase + ldRow) * K + ldCol;
    const float* Wptr = W + (size_t)(colBase + ldRow) * K + ldCol;

    float acc[TM][TN] = {};

    for (int kt = 0; kt < K; kt += BK) {
        float4 a = *(const float4*)(Aptr + kt);
        float4 w = *(const float4*)(Wptr + kt);
        As[ldCol + 0][ldRow] = a.x;
        As[ldCol + 1][ldRow] = a.y;
        As[ldCol + 2][ldRow] = a.z;
        As[ldCol + 3][ldRow] = a.w;
        Bs[ldCol + 0][ldRow] = w.x;
        Bs[ldCol + 1][ldRow] = w.y;
        Bs[ldCol + 2][ldRow] = w.z;
        Bs[ldCol + 3][ldRow] = w.w;
        __syncthreads();

        #pragma unroll
        for (int k = 0; k < BK; ++k) {
            float ra[TM], rb[TN];
            *(float4*)&ra[0] = *(const float4*)&As[k][ty * TM];
            *(float4*)&ra[4] = *(const float4*)&As[k][ty * TM + 4];
            *(float4*)&rb[0] = *(const float4*)&Bs[k][tx * TN];
            *(float4*)&rb[4] = *(const float4*)&Bs[k][tx * TN + 4];
            #pragma unroll
            for (int i = 0; i < TM; ++i)
                #pragma unroll
                for (int j = 0; j < TN; ++j)
                    acc[i][j] = fmaf(ra[i], rb[j], acc[i][j]);
        }
        __syncthreads();
    }

    // Epilogue: add bias, vectorized stores
    float bj[TN];
    #pragma unroll
    for (int j = 0; j < TN; ++j)
        bj[j] = bias[colBase + tx * TN + j];

    #pragma unroll
    for (int i = 0; i < TM; ++i) {
        float* cp = C + (size_t)(rowBase + ty * TM + i) * N + colBase + tx * TN;
        float4 v0, v1;
        v0.x = acc[i][0] + bj[0];  v0.y = acc[i][1] + bj[1];
        v0.z = acc[i][2] + bj[2];  v0.w = acc[i][3] + bj[3];
        v1.x = acc[i][4] + bj[4];  v1.y = acc[i][5] + bj[5];
        v1.z = acc[i][6] + bj[6];  v1.w = acc[i][7] + bj[7];
        *(float4*)cp       = v0;
        *(float4*)(cp + 4) = v1;
    }
}

// ---------------------------------------------------------------------------
// Scan: linear-space minGRU recurrence, one thread per (b, h) chain.
// Reads g_gh.  out == nullptr -> write layer-0 output into g_h1.
// h[t] = sigmoid(-gate)*h[t-1] + sigmoid(gate)*g(hidden),
//   g(x) = x + 0.5  (x >= 0)   else  sigmoid(x)
// Rewritten:  h = r * (e_g * h + gval),   e_g = exp(-gate), r = 1/(1+e_g)
// ---------------------------------------------------------------------------
__global__ __launch_bounds__(128) void scan_kernel(
    float* __restrict__ outp,
    float* __restrict__ lasth)
{
    const int tid = blockIdx.x * blockDim.x + threadIdx.x;   // b*HID + h
    const int b = tid / HID;
    const int h = tid % HID;

    float* out = outp ? outp : g_h1;

    const float* gp = g_gh + (size_t)b * SEQ * NCOLS + h;    // gate stream
    float* op = out + (size_t)b * SEQ * HID + h;

    float hp = 0.5f;

    #pragma unroll 4
    for (int t = 0; t < SEQ; ++t) {
        float gate = gp[(size_t)t * NCOLS];
        float hid  = gp[(size_t)t * NCOLS + HID];

        // clamp for inf-safety (values are ~N(0,1); clamp is a no-op in practice)
        gate = fminf(fmaxf(gate, -30.0f), 30.0f);

        float eg = __expf(-gate);
        float r  = __fdividef(1.0f, 1.0f + eg);

        // g(hidden): branchless both-paths
        float eh   = __expf(fminf(hid, 0.0f));                 // hid<0 path, safe
        float gneg = eh * __fdividef(1.0f, 1.0f + eh);
        float gpos = hid + 0.5f;
        float gval = (hid >= 0.0f) ? gpos : gneg;

        hp = r * fmaf(eg, hp, gval);
        op[(size_t)t * HID] = hp;
    }
    lasth[tid] = hp;
}

// ---------------------------------------------------------------------------
// Launch
// ---------------------------------------------------------------------------
extern "C" void kernel_launch(void* const* d_in, const int* in_sizes, int n_in,
                              void* d_out, int out_size)
{
    const float* x  = (const float*)d_in[0];
    const float* w0 = (const float*)d_in[1];
    const float* b0 = (const float*)d_in[2];
    const float* w1 = (const float*)d_in[3];
    const float* b1 = (const float*)d_in[4];
    float* out = (float*)d_out;

    // Output layout: out[B,S,H] (16777216 floats), then stacked next_hidden
    // (2,B,1,H): layer-0 last state at +16777216, layer-1 at +16777216+4096.
    float* nh0 = out + (size_t)MROWS * HID;
    float* nh1 = nh0 + BATCH * HID;

    dim3 gemmGrid(NCOLS / BN, MROWS / BM);   // (8, 256)
    const int scanBlocks = (BATCH * HID) / 128;

    // Layer 0
    sgemm_bias_kernel<<<gemmGrid, 256>>>(x, w0, b0, MROWS, NCOLS, DIN);
    scan_kernel<<<scanBlocks, 128>>>(nullptr, nh0);   // -> g_h1

    // Layer 1
    sgemm_bias_kernel<<<gemmGrid, 256>>>(nullptr, w1, b1, MROWS, NCOLS, HID);
    scan_kernel<<<scanBlocks, 128>>>(out, nh1);
}

// round 3
// speedup vs baseline: 4.6040x; 4.6040x over previous
#include <cuda_runtime.h>
#include <cstdint>
#include <cstddef>

// Problem constants
#define BATCH 8
#define SEQ   4096
#define HID   512
#define KDIM  512          // K for both layers (D=H=512)
#define NCOLS 1024         // 2*HID
#define MROWS (BATCH*SEQ)  // 32768

// Scratch (device globals -- allocation-free per harness rules)
// g_gh holds POST-activation (a, g~): cols [0,512) = a = sigmoid(-gate),
// cols [512,1024) = g~ = g(hidden).
__device__ float g_gh[(size_t)MROWS * NCOLS];  // 128 MB
__device__ float g_h1[(size_t)MROWS * HID];    //  64 MB

// ---------------------------------------------------------------------------
// TF32 tensor-core GEMM + fused activation epilogue
// C(M x N) = act( A(M x K) @ W(N x K)^T + bias )
// Tile: 128x128x16, 256 threads (8 warps, 2(m) x 4(n), warp tile 64x32),
// mma.sync.m16n8k8.tf32, double-buffered smem, ldmatrix fragments.
// ---------------------------------------------------------------------------
#define BM 128
#define BN 128
#define BKF 16      // k floats per stage
#define ROWW 20     // smem row stride in words (16 data + 4 pad; conflict-free ldmatrix)
#define NSTAGES (KDIM/BKF)   // 32

__device__ __forceinline__ uint32_t cvt_tf32(float f) {
    uint32_t r;
    asm("cvt.rna.tf32.f32 %0, %1;" : "=r"(r) : "f"(f));
    return r;
}

__device__ __forceinline__ float act_gate(float v) {
    // sigmoid(-v)
    v = fminf(fmaxf(v, -30.0f), 30.0f);
    float e = __expf(v);
    return __fdividef(1.0f, 1.0f + e);
}

__device__ __forceinline__ float act_hid(float v) {
    // g(v): v>=0 -> v+0.5 ; else sigmoid(v)
    float e = __expf(fminf(v, 0.0f));
    float s = e * __fdividef(1.0f, 1.0f + e);
    return v >= 0.0f ? v + 0.5f : s;
}

__global__ __launch_bounds__(256)
void gemm_act_kernel(const float* __restrict__ Ain,
                     const float* __restrict__ W,
                     const float* __restrict__ bias)
{
    const float* A = Ain ? Ain : g_h1;
    float* C = g_gh;

    __shared__ float sA[2][BM * ROWW];
    __shared__ float sB[2][BN * ROWW];

    const int tid  = threadIdx.x;
    const int lane = tid & 31;
    const int warp = tid >> 5;
    const int warpM = warp & 1;   // 0..1  -> 64 rows each
    const int warpN = warp >> 1;  // 0..3  -> 32 cols each
    const int rowBase = blockIdx.y * BM;
    const int colBase = blockIdx.x * BN;

    // Global->smem load mapping: 512 float4 slots per tile; thread owns slots {tid, tid+256}
    const int r0 = tid >> 2;        // 0..63
    const int c0 = tid & 3;         // chunk 0..3 (16B units along k)
    const float* Ag = A + (size_t)(rowBase + r0) * KDIM + c0 * 4;
    const float* Bg = W + (size_t)(colBase + r0) * KDIM + c0 * 4;
    const int sOff0 = r0 * ROWW + c0 * 4;
    const int sOff1 = (r0 + 64) * ROWW + c0 * 4;

    const uint32_t sAbase = (uint32_t)__cvta_generic_to_shared(&sA[0][0]);
    const uint32_t sBbase = (uint32_t)__cvta_generic_to_shared(&sB[0][0]);

    float acc[4][4][4];
    #pragma unroll
    for (int i = 0; i < 4; ++i)
        #pragma unroll
        for (int j = 0; j < 4; ++j)
            #pragma unroll
            for (int k = 0; k < 4; ++k)
                acc[i][j][k] = 0.0f;

    // ---- prologue: load stage 0 ----
    float4 va0 = *(const float4*)(Ag);
    float4 va1 = *(const float4*)(Ag + (size_t)64 * KDIM);
    float4 vb0 = *(const float4*)(Bg);
    float4 vb1 = *(const float4*)(Bg + (size_t)64 * KDIM);
    {
        uint32_t* pa0 = (uint32_t*)&sA[0][sOff0];
        pa0[0]=cvt_tf32(va0.x); pa0[1]=cvt_tf32(va0.y); pa0[2]=cvt_tf32(va0.z); pa0[3]=cvt_tf32(va0.w);
        uint32_t* pa1 = (uint32_t*)&sA[0][sOff1];
        pa1[0]=cvt_tf32(va1.x); pa1[1]=cvt_tf32(va1.y); pa1[2]=cvt_tf32(va1.z); pa1[3]=cvt_tf32(va1.w);
        uint32_t* pb0 = (uint32_t*)&sB[0][sOff0];
        pb0[0]=cvt_tf32(vb0.x); pb0[1]=cvt_tf32(vb0.y); pb0[2]=cvt_tf32(vb0.z); pb0[3]=cvt_tf32(vb0.w);
        uint32_t* pb1 = (uint32_t*)&sB[0][sOff1];
        pb1[0]=cvt_tf32(vb1.x); pb1[1]=cvt_tf32(vb1.y); pb1[2]=cvt_tf32(vb1.z); pb1[3]=cvt_tf32(vb1.w);
    }
    __syncthreads();

    // precomputed fragment address offsets (bytes), per ks added later
    const int aRow = warpM * 64 + (lane & 15);
    const int aChunkSel = lane >> 4;            // 0/1
    const int bRow = warpN * 32 + (lane & 7);
    const int bChunkSel = (lane >> 3) & 1;      // 0/1

    int buf = 0;
    #pragma unroll 1
    for (int kt = 0; kt < NSTAGES; ++kt) {
        // prefetch next stage to registers
        float4 na0, na1, nb0, nb1;
        if (kt + 1 < NSTAGES) {
            const float* Agn = Ag + (kt + 1) * BKF;
            const float* Bgn = Bg + (kt + 1) * BKF;
            na0 = *(const float4*)(Agn);
            na1 = *(const float4*)(Agn + (size_t)64 * KDIM);
            nb0 = *(const float4*)(Bgn);
            nb1 = *(const float4*)(Bgn + (size_t)64 * KDIM);
        }

        const uint32_t aBuf = sAbase + (uint32_t)buf * (BM * ROWW * 4);
        const uint32_t bBuf = sBbase + (uint32_t)buf * (BN * ROWW * 4);

        #pragma unroll
        for (int ks = 0; ks < 2; ++ks) {
            uint32_t afr[4][4];
            uint32_t bfr[4][2];
            #pragma unroll
            for (int mt = 0; mt < 4; ++mt) {
                uint32_t addr = aBuf + ((aRow + mt * 16) * ROWW + (2 * ks + aChunkSel) * 4) * 4;
                asm volatile("ldmatrix.sync.aligned.m8n8.x4.shared.b16 {%0,%1,%2,%3}, [%4];"
                    : "=r"(afr[mt][0]), "=r"(afr[mt][1]), "=r"(afr[mt][2]), "=r"(afr[mt][3])
                    : "r"(addr));
            }
            #pragma unroll
            for (int nt = 0; nt < 4; ++nt) {
                uint32_t addr = bBuf + ((bRow + nt * 8) * ROWW + (2 * ks + bChunkSel) * 4) * 4;
                asm volatile("ldmatrix.sync.aligned.m8n8.x2.shared.b16 {%0,%1}, [%2];"
                    : "=r"(bfr[nt][0]), "=r"(bfr[nt][1])
                    : "r"(addr));
            }
            #pragma unroll
            for (int mt = 0; mt < 4; ++mt)
                #pragma unroll
                for (int nt = 0; nt < 4; ++nt) {
                    asm volatile(
                        "mma.sync.aligned.m16n8k8.row.col.f32.tf32.tf32.f32 "
                        "{%0,%1,%2,%3}, {%4,%5,%6,%7}, {%8,%9}, {%0,%1,%2,%3};"
                        : "+f"(acc[mt][nt][0]), "+f"(acc[mt][nt][1]),
                          "+f"(acc[mt][nt][2]), "+f"(acc[mt][nt][3])
                        : "r"(afr[mt][0]), "r"(afr[mt][1]), "r"(afr[mt][2]), "r"(afr[mt][3]),
                          "r"(bfr[nt][0]), "r"(bfr[nt][1]));
                }
        }

        if (kt + 1 < NSTAGES) {
            int nb = buf ^ 1;
            uint32_t* pa0 = (uint32_t*)&sA[nb][sOff0];
            pa0[0]=cvt_tf32(na0.x); pa0[1]=cvt_tf32(na0.y); pa0[2]=cvt_tf32(na0.z); pa0[3]=cvt_tf32(na0.w);
            uint32_t* pa1 = (uint32_t*)&sA[nb][sOff1];
            pa1[0]=cvt_tf32(na1.x); pa1[1]=cvt_tf32(na1.y); pa1[2]=cvt_tf32(na1.z); pa1[3]=cvt_tf32(na1.w);
            uint32_t* pb0 = (uint32_t*)&sB[nb][sOff0];
            pb0[0]=cvt_tf32(nb0.x); pb0[1]=cvt_tf32(nb0.y); pb0[2]=cvt_tf32(nb0.z); pb0[3]=cvt_tf32(nb0.w);
            uint32_t* pb1 = (uint32_t*)&sB[nb][sOff1];
            pb1[0]=cvt_tf32(nb1.x); pb1[1]=cvt_tf32(nb1.y); pb1[2]=cvt_tf32(nb1.z); pb1[3]=cvt_tf32(nb1.w);
        }
        __syncthreads();
        buf ^= 1;
    }

    // ---- epilogue: bias + activation + store ----
    const bool isGate = (colBase < HID);
    const int g = lane >> 2;
    const int q = lane & 3;

    #pragma unroll
    for (int nt = 0; nt < 4; ++nt) {
        const int col = colBase + warpN * 32 + nt * 8 + q * 2;
        float2 bv = *(const float2*)(bias + col);
        #pragma unroll
        for (int mt = 0; mt < 4; ++mt) {
            const int row0 = rowBase + warpM * 64 + mt * 16 + g;
            float v00 = acc[mt][nt][0] + bv.x;
            float v01 = acc[mt][nt][1] + bv.y;
            float v10 = acc[mt][nt][2] + bv.x;
            float v11 = acc[mt][nt][3] + bv.y;
            float2 o0, o1;
            if (isGate) {
                o0.x = act_gate(v00); o0.y = act_gate(v01);
                o1.x = act_gate(v10); o1.y = act_gate(v11);
            } else {
                o0.x = act_hid(v00); o0.y = act_hid(v01);
                o1.x = act_hid(v10); o1.y = act_hid(v11);
            }
            *(float2*)(C + (size_t)row0 * NCOLS + col) = o0;
            *(float2*)(C + (size_t)(row0 + 8) * NCOLS + col) = o1;
        }
    }
}

// ---------------------------------------------------------------------------
// Scan: h[t] = a[t]*h[t-1] + (1-a[t])*g[t], with a,g precomputed in g_gh.
// One thread per (b,h) chain; unroll-8 register prefetch for MLP.
// outp == nullptr -> write into g_h1 (layer-0).
// ---------------------------------------------------------------------------
__global__ __launch_bounds__(64)
void scan_kernel(float* __restrict__ outp, float* __restrict__ lasth)
{
    const int tid = blockIdx.x * blockDim.x + threadIdx.x;  // b*HID + h
    const int b = tid >> 9;
    const int h = tid & 511;

    float* out = outp ? outp : g_h1;

    const float* pa = g_gh + (size_t)b * SEQ * NCOLS + h;        // a at [t][h]
    const float* pg = pa + HID;                                   // g at [t][h+512]
    float* op = out + (size_t)b * SEQ * HID + h;

    float hp = 0.5f;

    float Ac[8], Gc[8];
    #pragma unroll
    for (int i = 0; i < 8; ++i) {
        Ac[i] = pa[(size_t)i * NCOLS];
        Gc[i] = pg[(size_t)i * NCOLS];
    }

    for (int t0 = 0; t0 < SEQ; t0 += 8) {
        float An[8], Gn[8];
        if (t0 + 8 < SEQ) {
            #pragma unroll
            for (int i = 0; i < 8; ++i) {
                An[i] = pa[(size_t)(t0 + 8 + i) * NCOLS];
                Gn[i] = pg[(size_t)(t0 + 8 + i) * NCOLS];
            }
        }
        #pragma unroll
        for (int i = 0; i < 8; ++i) {
            float bb = __fmaf_rn(-Ac[i], Gc[i], Gc[i]);   // (1-a)*g, off critical path
            hp = __fmaf_rn(Ac[i], hp, bb);                // 1 FMA on the chain
            op[(size_t)(t0 + i) * HID] = hp;
        }
        #pragma unroll
        for (int i = 0; i < 8; ++i) { Ac[i] = An[i]; Gc[i] = Gn[i]; }
    }
    lasth[tid] = hp;
}

// ---------------------------------------------------------------------------
// Launch
// ---------------------------------------------------------------------------
extern "C" void kernel_launch(void* const* d_in, const int* in_sizes, int n_in,
                              void* d_out, int out_size)
{
    const float* x  = (const float*)d_in[0];
    const float* w0 = (const float*)d_in[1];
    const float* b0 = (const float*)d_in[2];
    const float* w1 = (const float*)d_in[3];
    const float* b1 = (const float*)d_in[4];
    float* out = (float*)d_out;

    float* nh0 = out + (size_t)MROWS * HID;   // next_hidden layer 0
    float* nh1 = nh0 + BATCH * HID;           // next_hidden layer 1

    dim3 gemmGrid(NCOLS / BN, MROWS / BM);    // (8, 256)
    const int scanBlocks = (BATCH * HID) / 64;

    gemm_act_kernel<<<gemmGrid, 256>>>(x, w0, b0);
    scan_kernel<<<scanBlocks, 64>>>(nullptr, nh0);     // -> g_h1
    gemm_act_kernel<<<gemmGrid, 256>>>(nullptr, w1, b1);
    scan_kernel<<<scanBlocks, 64>>>(out, nh1);
}

// round 4
// speedup vs baseline: 8.0335x; 1.7449x over previous
#include <cuda_runtime.h>
#include <cstdint>
#include <cstddef>

// Problem constants
#define BATCH 8
#define SEQ   4096
#define HID   512
#define KDIM  512          // K for both layers (D=H=512)
#define NCOLS 1024         // 2*HID
#define MROWS (BATCH*SEQ)  // 32768
#define NCHAIN (BATCH*HID) // 4096 independent recurrence chains

// Chunked scan config
#define NCHUNK 64
#define CHUNK  (SEQ/NCHUNK)   // 64

// Scratch (device globals -- allocation-free per harness rules)
// g_gh holds POST-activation (a, g~): cols [0,512) = a = sigmoid(-gate),
// cols [512,1024) = g~ = g(hidden).
__device__ float g_gh[(size_t)MROWS * NCOLS];   // 128 MB
__device__ float g_h1[(size_t)MROWS * HID];     //  64 MB
__device__ float g_cA[NCHUNK][NCHAIN];          // chunk composite coeff
__device__ float g_cB[NCHUNK][NCHAIN];          // chunk composite offset
__device__ float g_hs[NCHUNK][NCHAIN];          // chunk-start hidden state

// ---------------------------------------------------------------------------
// TF32 tensor-core GEMM + fused activation epilogue (unchanged from R1)
// C(M x N) = act( A(M x K) @ W(N x K)^T + bias )
// ---------------------------------------------------------------------------
#define BM 128
#define BN 128
#define BKF 16
#define ROWW 20
#define NSTAGES (KDIM/BKF)

__device__ __forceinline__ uint32_t cvt_tf32(float f) {
    uint32_t r;
    asm("cvt.rna.tf32.f32 %0, %1;" : "=r"(r) : "f"(f));
    return r;
}

__device__ __forceinline__ float act_gate(float v) {
    v = fminf(fmaxf(v, -30.0f), 30.0f);
    float e = __expf(v);
    return __fdividef(1.0f, 1.0f + e);
}

__device__ __forceinline__ float act_hid(float v) {
    float e = __expf(fminf(v, 0.0f));
    float s = e * __fdividef(1.0f, 1.0f + e);
    return v >= 0.0f ? v + 0.5f : s;
}

__global__ __launch_bounds__(256)
void gemm_act_kernel(const float* __restrict__ Ain,
                     const float* __restrict__ W,
                     const float* __restrict__ bias)
{
    const float* A = Ain ? Ain : g_h1;
    float* C = g_gh;

    __shared__ float sA[2][BM * ROWW];
    __shared__ float sB[2][BN * ROWW];

    const int tid  = threadIdx.x;
    const int lane = tid & 31;
    const int warp = tid >> 5;
    const int warpM = warp & 1;
    const int warpN = warp >> 1;
    const int rowBase = blockIdx.y * BM;
    const int colBase = blockIdx.x * BN;

    const int r0 = tid >> 2;
    const int c0 = tid & 3;
    const float* Ag = A + (size_t)(rowBase + r0) * KDIM + c0 * 4;
    const float* Bg = W + (size_t)(colBase + r0) * KDIM + c0 * 4;
    const int sOff0 = r0 * ROWW + c0 * 4;
    const int sOff1 = (r0 + 64) * ROWW + c0 * 4;

    const uint32_t sAbase = (uint32_t)__cvta_generic_to_shared(&sA[0][0]);
    const uint32_t sBbase = (uint32_t)__cvta_generic_to_shared(&sB[0][0]);

    float acc[4][4][4];
    #pragma unroll
    for (int i = 0; i < 4; ++i)
        #pragma unroll
        for (int j = 0; j < 4; ++j)
            #pragma unroll
            for (int k = 0; k < 4; ++k)
                acc[i][j][k] = 0.0f;

    float4 va0 = *(const float4*)(Ag);
    float4 va1 = *(const float4*)(Ag + (size_t)64 * KDIM);
    float4 vb0 = *(const float4*)(Bg);
    float4 vb1 = *(const float4*)(Bg + (size_t)64 * KDIM);
    {
        uint32_t* pa0 = (uint32_t*)&sA[0][sOff0];
        pa0[0]=cvt_tf32(va0.x); pa0[1]=cvt_tf32(va0.y); pa0[2]=cvt_tf32(va0.z); pa0[3]=cvt_tf32(va0.w);
        uint32_t* pa1 = (uint32_t*)&sA[0][sOff1];
        pa1[0]=cvt_tf32(va1.x); pa1[1]=cvt_tf32(va1.y); pa1[2]=cvt_tf32(va1.z); pa1[3]=cvt_tf32(va1.w);
        uint32_t* pb0 = (uint32_t*)&sB[0][sOff0];
        pb0[0]=cvt_tf32(vb0.x); pb0[1]=cvt_tf32(vb0.y); pb0[2]=cvt_tf32(vb0.z); pb0[3]=cvt_tf32(vb0.w);
        uint32_t* pb1 = (uint32_t*)&sB[0][sOff1];
        pb1[0]=cvt_tf32(vb1.x); pb1[1]=cvt_tf32(vb1.y); pb1[2]=cvt_tf32(vb1.z); pb1[3]=cvt_tf32(vb1.w);
    }
    __syncthreads();

    const int aRow = warpM * 64 + (lane & 15);
    const int aChunkSel = lane >> 4;
    const int bRow = warpN * 32 + (lane & 7);
    const int bChunkSel = (lane >> 3) & 1;

    int buf = 0;
    #pragma unroll 1
    for (int kt = 0; kt < NSTAGES; ++kt) {
        float4 na0, na1, nb0, nb1;
        if (kt + 1 < NSTAGES) {
            const float* Agn = Ag + (kt + 1) * BKF;
            const float* Bgn = Bg + (kt + 1) * BKF;
            na0 = *(const float4*)(Agn);
            na1 = *(const float4*)(Agn + (size_t)64 * KDIM);
            nb0 = *(const float4*)(Bgn);
            nb1 = *(const float4*)(Bgn + (size_t)64 * KDIM);
        }

        const uint32_t aBuf = sAbase + (uint32_t)buf * (BM * ROWW * 4);
        const uint32_t bBuf = sBbase + (uint32_t)buf * (BN * ROWW * 4);

        #pragma unroll
        for (int ks = 0; ks < 2; ++ks) {
            uint32_t afr[4][4];
            uint32_t bfr[4][2];
            #pragma unroll
            for (int mt = 0; mt < 4; ++mt) {
                uint32_t addr = aBuf + ((aRow + mt * 16) * ROWW + (2 * ks + aChunkSel) * 4) * 4;
                asm volatile("ldmatrix.sync.aligned.m8n8.x4.shared.b16 {%0,%1,%2,%3}, [%4];"
                    : "=r"(afr[mt][0]), "=r"(afr[mt][1]), "=r"(afr[mt][2]), "=r"(afr[mt][3])
                    : "r"(addr));
            }
            #pragma unroll
            for (int nt = 0; nt < 4; ++nt) {
                uint32_t addr = bBuf + ((bRow + nt * 8) * ROWW + (2 * ks + bChunkSel) * 4) * 4;
                asm volatile("ldmatrix.sync.aligned.m8n8.x2.shared.b16 {%0,%1}, [%2];"
                    : "=r"(bfr[nt][0]), "=r"(bfr[nt][1])
                    : "r"(addr));
            }
            #pragma unroll
            for (int mt = 0; mt < 4; ++mt)
                #pragma unroll
                for (int nt = 0; nt < 4; ++nt) {
                    asm volatile(
                        "mma.sync.aligned.m16n8k8.row.col.f32.tf32.tf32.f32 "
                        "{%0,%1,%2,%3}, {%4,%5,%6,%7}, {%8,%9}, {%0,%1,%2,%3};"
                        : "+f"(acc[mt][nt][0]), "+f"(acc[mt][nt][1]),
                          "+f"(acc[mt][nt][2]), "+f"(acc[mt][nt][3])
                        : "r"(afr[mt][0]), "r"(afr[mt][1]), "r"(afr[mt][2]), "r"(afr[mt][3]),
                          "r"(bfr[nt][0]), "r"(bfr[nt][1]));
                }
        }

        if (kt + 1 < NSTAGES) {
            int nb = buf ^ 1;
            uint32_t* pa0 = (uint32_t*)&sA[nb][sOff0];
            pa0[0]=cvt_tf32(na0.x); pa0[1]=cvt_tf32(na0.y); pa0[2]=cvt_tf32(na0.z); pa0[3]=cvt_tf32(na0.w);
            uint32_t* pa1 = (uint32_t*)&sA[nb][sOff1];
            pa1[0]=cvt_tf32(na1.x); pa1[1]=cvt_tf32(na1.y); pa1[2]=cvt_tf32(na1.z); pa1[3]=cvt_tf32(na1.w);
            uint32_t* pb0 = (uint32_t*)&sB[nb][sOff0];
            pb0[0]=cvt_tf32(nb0.x); pb0[1]=cvt_tf32(nb0.y); pb0[2]=cvt_tf32(nb0.z); pb0[3]=cvt_tf32(nb0.w);
            uint32_t* pb1 = (uint32_t*)&sB[nb][sOff1];
            pb1[0]=cvt_tf32(nb1.x); pb1[1]=cvt_tf32(nb1.y); pb1[2]=cvt_tf32(nb1.z); pb1[3]=cvt_tf32(nb1.w);
        }
        __syncthreads();
        buf ^= 1;
    }

    const bool isGate = (colBase < HID);
    const int g = lane >> 2;
    const int q = lane & 3;

    #pragma unroll
    for (int nt = 0; nt < 4; ++nt) {
        const int col = colBase + warpN * 32 + nt * 8 + q * 2;
        float2 bv = *(const float2*)(bias + col);
        #pragma unroll
        for (int mt = 0; mt < 4; ++mt) {
            const int row0 = rowBase + warpM * 64 + mt * 16 + g;
            float v00 = acc[mt][nt][0] + bv.x;
            float v01 = acc[mt][nt][1] + bv.y;
            float v10 = acc[mt][nt][2] + bv.x;
            float v11 = acc[mt][nt][3] + bv.y;
            float2 o0, o1;
            if (isGate) {
                o0.x = act_gate(v00); o0.y = act_gate(v01);
                o1.x = act_gate(v10); o1.y = act_gate(v11);
            } else {
                o0.x = act_hid(v00); o0.y = act_hid(v01);
                o1.x = act_hid(v10); o1.y = act_hid(v11);
            }
            *(float2*)(C + (size_t)row0 * NCOLS + col) = o0;
            *(float2*)(C + (size_t)(row0 + 8) * NCOLS + col) = o1;
        }
    }
}

// ---------------------------------------------------------------------------
// Chunked parallel scan.  h[t] = a[t]*h[t-1] + b[t],  b = (1-a)*g.
// Pass 1: per-(chain, chunk) thread composes its 64 steps into (A, B).
// Pass 2: per-chain thread scans the 64 chunk composites -> chunk-start h.
// Pass 3: per-(chain, chunk) thread re-walks its chunk from the known start.
// ---------------------------------------------------------------------------
__global__ __launch_bounds__(256)
void scan_pass1(void)
{
    const int id = blockIdx.x * 256 + threadIdx.x;     // 262144 threads
    const int chunk = id >> 12;                         // / NCHAIN
    const int chain = id & (NCHAIN - 1);
    const int b = chain >> 9;
    const int h = chain & 511;

    const float* pa = g_gh + ((size_t)(b * SEQ + chunk * CHUNK)) * NCOLS + h;

    float A = 1.0f, Bv = 0.0f;
    #pragma unroll 8
    for (int t = 0; t < CHUNK; ++t) {
        float a = pa[(size_t)t * NCOLS];
        float g = pa[(size_t)t * NCOLS + HID];
        float bb = __fmaf_rn(-a, g, g);       // (1-a)*g
        A  = A * a;
        Bv = __fmaf_rn(a, Bv, bb);
    }
    g_cA[chunk][chain] = A;
    g_cB[chunk][chain] = Bv;
}

__global__ __launch_bounds__(256)
void scan_pass2(float* __restrict__ lasth)
{
    const int chain = blockIdx.x * 256 + threadIdx.x;  // 4096 threads

    float run = 0.5f;
    #pragma unroll 8
    for (int c = 0; c < NCHUNK; ++c) {
        g_hs[c][chain] = run;
        float A = g_cA[c][chain];
        float B = g_cB[c][chain];
        run = __fmaf_rn(A, run, B);
    }
    lasth[chain] = run;
}

__global__ __launch_bounds__(256)
void scan_pass3(float* __restrict__ outp)
{
    const int id = blockIdx.x * 256 + threadIdx.x;
    const int chunk = id >> 12;
    const int chain = id & (NCHAIN - 1);
    const int b = chain >> 9;
    const int h = chain & 511;

    float* out = outp ? outp : g_h1;

    const float* pa = g_gh + ((size_t)(b * SEQ + chunk * CHUNK)) * NCOLS + h;
    float* op = out + ((size_t)(b * SEQ + chunk * CHUNK)) * HID + h;

    float hp = g_hs[chunk][chain];
    #pragma unroll 8
    for (int t = 0; t < CHUNK; ++t) {
        float a = pa[(size_t)t * NCOLS];
        float g = pa[(size_t)t * NCOLS + HID];
        float bb = __fmaf_rn(-a, g, g);
        hp = __fmaf_rn(a, hp, bb);
        op[(size_t)t * HID] = hp;
    }
}

// ---------------------------------------------------------------------------
// Launch
// ---------------------------------------------------------------------------
extern "C" void kernel_launch(void* const* d_in, const int* in_sizes, int n_in,
                              void* d_out, int out_size)
{
    const float* x  = (const float*)d_in[0];
    const float* w0 = (const float*)d_in[1];
    const float* b0 = (const float*)d_in[2];
    const float* w1 = (const float*)d_in[3];
    const float* b1 = (const float*)d_in[4];
    float* out = (float*)d_out;

    float* nh0 = out + (size_t)MROWS * HID;   // next_hidden layer 0
    float* nh1 = nh0 + NCHAIN;                // next_hidden layer 1

    dim3 gemmGrid(NCOLS / BN, MROWS / BM);    // (8, 256)
    const int p13Blocks = (NCHUNK * NCHAIN) / 256;   // 1024
    const int p2Blocks  = NCHAIN / 256;              // 16

    // Layer 0
    gemm_act_kernel<<<gemmGrid, 256>>>(x, w0, b0);
    scan_pass1<<<p13Blocks, 256>>>();
    scan_pass2<<<p2Blocks, 256>>>(nh0);
    scan_pass3<<<p13Blocks, 256>>>(nullptr);          // -> g_h1

    // Layer 1
    gemm_act_kernel<<<gemmGrid, 256>>>(nullptr, w1, b1);
    scan_pass1<<<p13Blocks, 256>>>();
    scan_pass2<<<p2Blocks, 256>>>(nh1);
    scan_pass3<<<p13Blocks, 256>>>(out);
}

// round 8
// speedup vs baseline: 9.1537x; 1.1394x over previous
#include <cuda_runtime.h>
#include <cstdint>
#include <cstddef>

// Problem constants
#define BATCH 8
#define SEQ   4096
#define HID   512
#define KDIM  512
#define NCOLS 1024
#define MROWS (BATCH*SEQ)   // 32768
#define NCHAIN (BATCH*HID)  // 4096

// Chunked scan config
#define NCHUNK 64
#define CHUNK  (SEQ/NCHUNK) // 64

// Scratch (device globals -- allocation-free per harness rules)
__device__ float g_gh[(size_t)MROWS * NCOLS];   // 128 MB post-activation (a, g~)
__device__ float g_h1[(size_t)MROWS * HID];     //  64 MB layer-0 output (tf32-rounded)
__device__ float g_x [(size_t)MROWS * KDIM];    //  64 MB tf32-rounded X
__device__ float g_w0[(size_t)NCOLS * KDIM];    //   2 MB tf32-rounded w0
__device__ float g_w1[(size_t)NCOLS * HID];     //   2 MB tf32-rounded w1
__device__ float g_cA[NCHUNK][NCHAIN];
__device__ float g_cB[NCHUNK][NCHAIN];
__device__ float g_hs[NCHUNK][NCHAIN];

__device__ __forceinline__ uint32_t cvt_tf32(float f) {
    uint32_t r;
    asm("cvt.rna.tf32.f32 %0, %1;" : "=r"(r) : "f"(f));
    return r;
}
__device__ __forceinline__ float round_tf32(float f) {
    return __uint_as_float(cvt_tf32(f));
}

// ---------------------------------------------------------------------------
// Prep: round inputs to tf32 grid once (rna). which: 0=x, 1=w0, 2=w1.
// ---------------------------------------------------------------------------
__global__ __launch_bounds__(256)
void round_kernel(const float* __restrict__ src, int which, int n4)
{
    int i = blockIdx.x * 256 + threadIdx.x;
    if (i >= n4) return;
    float* dst = which == 0 ? g_x : which == 1 ? g_w0 : g_w1;
    float4 v = ((const float4*)src)[i];
    float4 o;
    o.x = round_tf32(v.x); o.y = round_tf32(v.y);
    o.z = round_tf32(v.z); o.w = round_tf32(v.w);
    ((float4*)dst)[i] = o;
}

// ---------------------------------------------------------------------------
// TF32 tensor-core GEMM, cp.async 4-stage pipeline, fused activation epilogue.
// Operands are pre-rounded to tf32 grid, so raw bits feed mma directly.
// C = act( A(M x K) @ W(N x K)^T + bias ), tile 128x128x16, 256 threads.
// ---------------------------------------------------------------------------
#define BM 128
#define BN 128
#define BKF 16
#define ROWW 20
#define NSTAGES (KDIM/BKF)   // 32
#define PSTAGES 4
#define STAGE_WORDS (BM*ROWW)            // 2560
#define GEMM_SMEM (PSTAGES*2*STAGE_WORDS*4)  // 81920 B

__device__ __forceinline__ float act_gate(float v) {
    v = fminf(fmaxf(v, -30.0f), 30.0f);
    float e = __expf(v);
    return __fdividef(1.0f, 1.0f + e);
}
__device__ __forceinline__ float act_hid(float v) {
    float e = __expf(fminf(v, 0.0f));
    float s = e * __fdividef(1.0f, 1.0f + e);
    return v >= 0.0f ? v + 0.5f : s;
}
__device__ __forceinline__ void cp16(uint32_t dst, const float* src) {
    asm volatile("cp.async.cg.shared.global [%0], [%1], 16;" :: "r"(dst), "l"(src));
}

__global__ __launch_bounds__(256)
void gemm_act_kernel(int layer, const float* __restrict__ bias)
{
    const float* A = layer ? g_h1 : g_x;
    const float* W = layer ? g_w1 : g_w0;
    float* C = g_gh;

    extern __shared__ float smem[];

    const int tid  = threadIdx.x;
    const int lane = tid & 31;
    const int warp = tid >> 5;
    const int warpM = warp & 1;
    const int warpN = warp >> 1;
    const int rowBase = blockIdx.y * BM;
    const int colBase = blockIdx.x * BN;

    const int r0 = tid >> 2;
    const int c0 = tid & 3;
    const float* Ag = A + (size_t)(rowBase + r0) * KDIM + c0 * 4;
    const float* Bg = W + (size_t)(colBase + r0) * KDIM + c0 * 4;
    const int sOff0 = r0 * ROWW + c0 * 4;
    const int sOff1 = (r0 + 64) * ROWW + c0 * 4;

    const uint32_t sAbase = (uint32_t)__cvta_generic_to_shared(&smem[0]);
    const uint32_t sBbase = sAbase + PSTAGES * STAGE_WORDS * 4;

    float acc[4][4][4];
    #pragma unroll
    for (int i = 0; i < 4; ++i)
        #pragma unroll
        for (int j = 0; j < 4; ++j)
            #pragma unroll
            for (int k = 0; k < 4; ++k)
                acc[i][j][k] = 0.0f;

    auto issue = [&](int kt, int stage) {
        const float* a0 = Ag + kt * BKF;
        const float* b0 = Bg + kt * BKF;
        uint32_t sw = (uint32_t)stage * (STAGE_WORDS * 4);
        cp16(sAbase + sw + sOff0 * 4, a0);
        cp16(sAbase + sw + sOff1 * 4, a0 + (size_t)64 * KDIM);
        cp16(sBbase + sw + sOff0 * 4, b0);
        cp16(sBbase + sw + sOff1 * 4, b0 + (size_t)64 * KDIM);
    };

    // prologue: stages 0..2
    #pragma unroll
    for (int s = 0; s < PSTAGES - 1; ++s) {
        issue(s, s);
        asm volatile("cp.async.commit_group;");
    }
    asm volatile("cp.async.wait_group %0;" :: "n"(PSTAGES - 2));
    __syncthreads();

    const int aRow = warpM * 64 + (lane & 15);
    const int aChunkSel = lane >> 4;
    const int bRow = warpN * 32 + (lane & 7);
    const int bChunkSel = (lane >> 3) & 1;

    #pragma unroll 1
    for (int kt = 0; kt < NSTAGES; ++kt) {
        const int buf = kt & (PSTAGES - 1);
        const uint32_t aBuf = sAbase + (uint32_t)buf * (STAGE_WORDS * 4);
        const uint32_t bBuf = sBbase + (uint32_t)buf * (STAGE_WORDS * 4);

        #pragma unroll
        for (int ks = 0; ks < 2; ++ks) {
            uint32_t afr[4][4];
            uint32_t bfr[4][2];
            #pragma unroll
            for (int mt = 0; mt < 4; ++mt) {
                uint32_t addr = aBuf + ((aRow + mt * 16) * ROWW + (2 * ks + aChunkSel) * 4) * 4;
                asm volatile("ldmatrix.sync.aligned.m8n8.x4.shared.b16 {%0,%1,%2,%3}, [%4];"
                    : "=r"(afr[mt][0]), "=r"(afr[mt][1]), "=r"(afr[mt][2]), "=r"(afr[mt][3])
                    : "r"(addr));
            }
            #pragma unroll
            for (int nt = 0; nt < 4; ++nt) {
                uint32_t addr = bBuf + ((bRow + nt * 8) * ROWW + (2 * ks + bChunkSel) * 4) * 4;
                asm volatile("ldmatrix.sync.aligned.m8n8.x2.shared.b16 {%0,%1}, [%2];"
                    : "=r"(bfr[nt][0]), "=r"(bfr[nt][1])
                    : "r"(addr));
            }
            #pragma unroll
            for (int mt = 0; mt < 4; ++mt)
                #pragma unroll
                for (int nt = 0; nt < 4; ++nt) {
                    asm volatile(
                        "mma.sync.aligned.m16n8k8.row.col.f32.tf32.tf32.f32 "
                        "{%0,%1,%2,%3}, {%4,%5,%6,%7}, {%8,%9}, {%0,%1,%2,%3};"
                        : "+f"(acc[mt][nt][0]), "+f"(acc[mt][nt][1]),
                          "+f"(acc[mt][nt][2]), "+f"(acc[mt][nt][3])
                        : "r"(afr[mt][0]), "r"(afr[mt][1]), "r"(afr[mt][2]), "r"(afr[mt][3]),
                          "r"(bfr[nt][0]), "r"(bfr[nt][1]));
                }
        }

        if (kt + PSTAGES - 1 < NSTAGES)
            issue(kt + PSTAGES - 1, (kt + PSTAGES - 1) & (PSTAGES - 1));
        asm volatile("cp.async.commit_group;");
        asm volatile("cp.async.wait_group %0;" :: "n"(PSTAGES - 2));
        __syncthreads();
    }

    // epilogue
    const bool isGate = (colBase < HID);
    const int g = lane >> 2;
    const int q = lane & 3;

    #pragma unroll
    for (int nt = 0; nt < 4; ++nt) {
        const int col = colBase + warpN * 32 + nt * 8 + q * 2;
        float2 bv = *(const float2*)(bias + col);
        #pragma unroll
        for (int mt = 0; mt < 4; ++mt) {
            const int row0 = rowBase + warpM * 64 + mt * 16 + g;
            float v00 = acc[mt][nt][0] + bv.x;
            float v01 = acc[mt][nt][1] + bv.y;
            float v10 = acc[mt][nt][2] + bv.x;
            float v11 = acc[mt][nt][3] + bv.y;
            float2 o0, o1;
            if (isGate) {
                o0.x = act_gate(v00); o0.y = act_gate(v01);
                o1.x = act_gate(v10); o1.y = act_gate(v11);
            } else {
                o0.x = act_hid(v00); o0.y = act_hid(v01);
                o1.x = act_hid(v10); o1.y = act_hid(v11);
            }
            *(float2*)(C + (size_t)row0 * NCOLS + col) = o0;
            *(float2*)(C + (size_t)(row0 + 8) * NCOLS + col) = o1;
        }
    }
}

// ---------------------------------------------------------------------------
// Chunked parallel scan, 2 chains per thread (float2 traffic).
// h[t] = a*h + (1-a)*g
// ---------------------------------------------------------------------------
__global__ __launch_bounds__(256)
void scan_pass1(void)
{
    const int id = blockIdx.x * 256 + threadIdx.x;   // NCHUNK*NCHAIN/2 = 131072
    const int chunk = id >> 11;
    const int cp = id & 2047;
    const int b = cp >> 8;
    const int h2 = (cp & 255) * 2;

    const float* base = g_gh + ((size_t)(b * SEQ + chunk * CHUNK)) * NCOLS + h2;

    float A0 = 1.0f, B0 = 0.0f, A1 = 1.0f, B1 = 0.0f;
    #pragma unroll 8
    for (int t = 0; t < CHUNK; ++t) {
        float2 a = *(const float2*)(base + (size_t)t * NCOLS);
        float2 g = *(const float2*)(base + (size_t)t * NCOLS + HID);
        float bb0 = __fmaf_rn(-a.x, g.x, g.x);
        float bb1 = __fmaf_rn(-a.y, g.y, g.y);
        A0 = A0 * a.x;  B0 = __fmaf_rn(a.x, B0, bb0);
        A1 = A1 * a.y;  B1 = __fmaf_rn(a.y, B1, bb1);
    }
    const int chain = b * HID + h2;
    *(float2*)&g_cA[chunk][chain] = make_float2(A0, A1);
    *(float2*)&g_cB[chunk][chain] = make_float2(B0, B1);
}

__global__ __launch_bounds__(256)
void scan_pass2(float* __restrict__ lasth)
{
    const int chain = blockIdx.x * 256 + threadIdx.x;  // 4096
    float run = 0.5f;
    #pragma unroll 8
    for (int c = 0; c < NCHUNK; ++c) {
        g_hs[c][chain] = run;
        run = __fmaf_rn(g_cA[c][chain], run, g_cB[c][chain]);
    }
    lasth[chain] = run;
}

__global__ __launch_bounds__(256)
void scan_pass3(float* __restrict__ outp)
{
    const int id = blockIdx.x * 256 + threadIdx.x;
    const int chunk = id >> 11;
    const int cp = id & 2047;
    const int b = cp >> 8;
    const int h2 = (cp & 255) * 2;
    const int chain = b * HID + h2;

    float* out = outp ? outp : g_h1;
    const bool roundOut = (outp == nullptr);   // layer-0: h feeds tf32 GEMM

    const float* base = g_gh + ((size_t)(b * SEQ + chunk * CHUNK)) * NCOLS + h2;
    float* op = out + ((size_t)(b * SEQ + chunk * CHUNK)) * HID + h2;

    float2 hs = *(const float2*)&g_hs[chunk][chain];
    float h0 = hs.x, h1v = hs.y;

    #pragma unroll 8
    for (int t = 0; t < CHUNK; ++t) {
        float2 a = *(const float2*)(base + (size_t)t * NCOLS);
        float2 g = *(const float2*)(base + (size_t)t * NCOLS + HID);
        float bb0 = __fmaf_rn(-a.x, g.x, g.x);
        float bb1 = __fmaf_rn(-a.y, g.y, g.y);
        h0  = __fmaf_rn(a.x, h0,  bb0);
        h1v = __fmaf_rn(a.y, h1v, bb1);
        float2 o;
        if (roundOut) { o.x = round_tf32(h0); o.y = round_tf32(h1v); }
        else          { o.x = h0;             o.y = h1v; }
        *(float2*)(op + (size_t)t * HID) = o;
    }
}

// ---------------------------------------------------------------------------
// Launch
// ---------------------------------------------------------------------------
extern "C" void kernel_launch(void* const* d_in, const int* in_sizes, int n_in,
                              void* d_out, int out_size)
{
    const float* x  = (const float*)d_in[0];
    const float* w0 = (const float*)d_in[1];
    const float* b0 = (const float*)d_in[2];
    const float* w1 = (const float*)d_in[3];
    const float* b1 = (const float*)d_in[4];
    float* out = (float*)d_out;

    float* nh0 = out + (size_t)MROWS * HID;
    float* nh1 = nh0 + NCHAIN;

    cudaFuncSetAttribute(gemm_act_kernel,
                         cudaFuncAttributeMaxDynamicSharedMemorySize, GEMM_SMEM);

    dim3 gemmGrid(NCOLS / BN, MROWS / BM);          // (8, 256)
    const int p13Blocks = (NCHUNK * NCHAIN / 2) / 256;  // 512
    const int p2Blocks  = NCHAIN / 256;                 // 16

    // Prep: tf32-round inputs
    const int xN4 = (MROWS * KDIM) / 4;     // 8388608
    const int wN4 = (NCOLS * KDIM) / 4;     // 131072
    round_kernel<<<xN4 / 256, 256>>>(x,  0, xN4);
    round_kernel<<<wN4 / 256, 256>>>(w0, 1, wN4);
    round_kernel<<<wN4 / 256, 256>>>(w1, 2, wN4);

    // Layer 0
    gemm_act_kernel<<<gemmGrid, 256, GEMM_SMEM>>>(0, b0);
    scan_pass1<<<p13Blocks, 256>>>();
    scan_pass2<<<p2Blocks, 256>>>(nh0);
    scan_pass3<<<p13Blocks, 256>>>(nullptr);        // -> g_h1 (tf32-rounded)

    // Layer 1
    gemm_act_kernel<<<gemmGrid, 256, GEMM_SMEM>>>(1, b1);
    scan_pass1<<<p13Blocks, 256>>>();
    scan_pass2<<<p2Blocks, 256>>>(nh1);
    scan_pass3<<<p13Blocks, 256>>>(out);
}